// round 16
// baseline (speedup 1.0000x reference)
#include <cuda_runtime.h>
#include <cuda_fp16.h>
#include <cstdint>

#define NN 100000
#define NE 1600000
#define D  128
#define NTILES ((NN + 127) / 128)   // 782
#define PW 136                       // padded row (halves): 272B -> conflict-free ldmatrix
#define DP (D * PW)                  // halves per 128-row padded array

// ---------------- scratch (device globals; allocation-free) ----------------
__device__ __half g_hs[NN * D];       // gather source: h * norm_src, fp16
__device__ __half g_Ah[NN * D];       // gemm input (aggregated), fp16 hi
__device__ __half g_Al[NN * D];       // gemm input (aggregated), fp16 lo
__device__ float  g_norm_src[NN];
__device__ float  g_norm_dst[NN];
__device__ int    g_deg_out[NN];
__device__ int    g_deg_in[NN];
__device__ int    g_row_start[NN];
__device__ int    g_cursor[NN];
__device__ int    g_col[NE];
__device__ int    g_alloc;
__device__ __half g_Whp[3 * DP];      // W^T fp16-hi, padded rows
__device__ __half g_Wlp[3 * DP];      // W^T fp16-lo, padded rows

// ---------------- helpers ----------------
__device__ __forceinline__ uint32_t smem_u32(const void* p) {
    uint32_t a;
    asm("{ .reg .u64 t; cvta.to.shared.u64 t, %1; cvt.u32.u64 %0, t; }" : "=r"(a) : "l"(p));
    return a;
}
__device__ __forceinline__ uint32_t h2_bits(__half2 h) {
    return *(const uint32_t*)&h;
}
__device__ __forceinline__ void acc_uint4(float* acc, uint4 v) {
    const __half2* hp = (const __half2*)&v;
#pragma unroll
    for (int j = 0; j < 4; j++) {
        float2 f = __half22float2(hp[j]);
        acc[2 * j]     += f.x;
        acc[2 * j + 1] += f.y;
    }
}

#define LDSM_X4(r, addr) \
    asm volatile("ldmatrix.sync.aligned.m8n8.x4.shared.b16 {%0,%1,%2,%3}, [%4];" \
        : "=r"((r)[0]), "=r"((r)[1]), "=r"((r)[2]), "=r"((r)[3]) : "r"(addr))

#define MMA16816(d, a, b0, b1) \
    asm volatile("mma.sync.aligned.m16n8k16.row.col.f32.f16.f16.f32 " \
        "{%0,%1,%2,%3}, {%4,%5,%6,%7}, {%8,%9}, {%0,%1,%2,%3};" \
        : "+f"((d)[0]), "+f"((d)[1]), "+f"((d)[2]), "+f"((d)[3]) \
        : "r"((a)[0]), "r"((a)[1]), "r"((a)[2]), "r"((a)[3]), "r"(b0), "r"(b1))

// ---------------- graph preprocessing ----------------
__global__ void k_init_deg() {
    int i = blockIdx.x * blockDim.x + threadIdx.x;
    if (i < NN) { g_deg_out[i] = 1; g_deg_in[i] = 1; }   // self-loop contributes 1
    if (i == 0) g_alloc = 0;
}

__global__ void k_count(const int* __restrict__ src, const int* __restrict__ dst) {
    int e = blockIdx.x * blockDim.x + threadIdx.x;
    if (e < NE) {
        atomicAdd(&g_deg_out[src[e]], 1);
        atomicAdd(&g_deg_in[dst[e]], 1);
    }
}

__global__ void k_norm_alloc() {
    int i = blockIdx.x * blockDim.x + threadIdx.x;
    int lane = threadIdx.x & 31;
    bool valid = i < NN;
    int din  = valid ? g_deg_in[i]  : 1;
    int dout = valid ? g_deg_out[i] : 1;
    if (valid) {
        g_norm_src[i] = rsqrtf((float)dout);
        g_norm_dst[i] = rsqrtf((float)din);
    }
    int d = din - 1;
    int p = d;
#pragma unroll
    for (int off = 1; off < 32; off <<= 1) {
        int v = __shfl_up_sync(0xffffffffu, p, off);
        if (lane >= off) p += v;
    }
    int total = __shfl_sync(0xffffffffu, p, 31);
    int base = 0;
    if (lane == 31) base = atomicAdd(&g_alloc, total);
    base = __shfl_sync(0xffffffffu, base, 31);
    int start = base + p - d;
    if (valid) { g_row_start[i] = start; g_cursor[i] = start; }
}

__global__ void k_fill(const int* __restrict__ src, const int* __restrict__ dst) {
    int e = blockIdx.x * blockDim.x + threadIdx.x;
    if (e < NE) {
        int p = atomicAdd(&g_cursor[dst[e]], 1);
        g_col[p] = src[e];
    }
}

// ---------------- W prep: W^T -> fp16 hi/lo, padded rows ----------------
__global__ void k_wprep(const float* __restrict__ Ws) {
    int idx = blockIdx.x * blockDim.x + threadIdx.x;
    if (idx >= 3 * D * D) return;
    int l = idx >> 14;
    int r = idx & 16383;
    int n = r >> 7;
    int k = r & 127;
    float v = Ws[(l << 14) + (k << 7) + n];          // W[l][k][n] = Wt[n][k]
    __half hi = __float2half_rn(v);
    __half lo = __float2half_rn(v - __half2float(hi));
    int o = l * DP + n * PW + k;
    g_Whp[o] = hi;
    g_Wlp[o] = lo;
    if (k < PW - D) {                                // zero the pad
        g_Whp[l * DP + n * PW + D + k] = __float2half_rn(0.f);
        g_Wlp[l * DP + n * PW + D + k] = __float2half_rn(0.f);
    }
}

// ---------------- layer-0 input scale: g_hs = fp16(input * norm_src) ----------
__global__ void k_scale0(const float* __restrict__ in) {
    int idx = blockIdx.x * blockDim.x + threadIdx.x;   // float4 / half4 index
    if (idx < NN * (D / 4)) {
        int row = idx >> 5;
        float s = g_norm_src[row];
        float4 v = ((const float4*)in)[idx];
        __half2 h0 = __floats2half2_rn(v.x * s, v.y * s);
        __half2 h1 = __floats2half2_rn(v.z * s, v.w * s);
        ((uint2*)g_hs)[idx] = make_uint2(h2_bits(h0), h2_bits(h1));
    }
}

// ---------------- aggregation: warp per node; 2 edges per LDG.128 -------------
// Lanes 0-15 handle even edges, lanes 16-31 odd edges; each lane reads 16B
// (8 halves) of a row. Partial sums merged with one shfl_xor(16) tree.
// Lanes 0-15 store g_Ah (fp16 hi), lanes 16-31 store g_Al (fp16 lo).
__global__ __launch_bounds__(256) void k_agg() {
    int gw   = (blockIdx.x * blockDim.x + threadIdx.x) >> 5;
    int lane = threadIdx.x & 31;
    if (gw >= NN) return;
    int half = lane >> 4;          // 0: even edges, 1: odd edges
    int hl   = lane & 15;          // 16B chunk index within row
    const uint4* __restrict__ h4 = (const uint4*)g_hs;   // 16 uint4 per row
    const int* __restrict__ col = g_col;

    float acc[8];
#pragma unroll
    for (int j = 0; j < 8; j++) acc[j] = 0.f;
    if (half == 0) acc_uint4(acc, h4[gw * 16 + hl]);     // self-loop (once)

    int s = g_row_start[gw];
    int e = s + g_deg_in[gw] - 1;
    int base = s;
    for (; base + 8 <= e; base += 8) {
        int c0 = col[base     + half];
        int c1 = col[base + 2 + half];
        int c2 = col[base + 4 + half];
        int c3 = col[base + 6 + half];
        uint4 v0 = h4[c0 * 16 + hl];
        uint4 v1 = h4[c1 * 16 + hl];
        uint4 v2 = h4[c2 * 16 + hl];
        uint4 v3 = h4[c3 * 16 + hl];
        acc_uint4(acc, v0);
        acc_uint4(acc, v1);
        acc_uint4(acc, v2);
        acc_uint4(acc, v3);
    }
    for (; base + 2 <= e; base += 2) {
        int c = col[base + half];
        acc_uint4(acc, h4[c * 16 + hl]);
    }
    if (base < e && half == 0) {                         // single trailing edge
        int c = col[base];
        acc_uint4(acc, h4[c * 16 + hl]);
    }

    // merge even/odd partials
#pragma unroll
    for (int j = 0; j < 8; j++)
        acc[j] += __shfl_xor_sync(0xffffffffu, acc[j], 16);

    float nd = g_norm_dst[gw];             // fold norm_dst here
    // fp16 hi/lo split; lanes 0-15 write hi, lanes 16-31 write lo
    __half outv[8];
#pragma unroll
    for (int j = 0; j < 8; j++) {
        float av = acc[j] * nd;
        __half hi = __float2half_rn(av);
        outv[j] = half ? __float2half_rn(av - __half2float(hi)) : hi;
    }
    __half* dst = half ? g_Al : g_Ah;
    *(uint4*)(&dst[gw * D + 8 * hl]) = *(const uint4*)outv;
}

// ---------------- HMMA GEMM: h = A @ W + b (persistent, all-smem operands) ----
// smem: W_h | W_l | A_h | A_l, all 128x128 padded to 136-half rows (139KB).
// Warp (wm,wc) owns 32 rows x 64 cols. A and B fragments both via ldmatrix.x4
// (conflict-free, stride 272B). Mainloop: 12 LDSM + 48 MMA per k-step per warp.
__global__ __launch_bounds__(256, 1) void k_gemm_mma(
    int layer, const float* __restrict__ bias,
    int relu_scale, float* __restrict__ fout)
{
    extern __shared__ __half sm[];              // [4][DP]
    __shared__ float s_bias[D];

    int tid  = threadIdx.x;
    int wid  = tid >> 5;
    int lane = tid & 31;
    int wm   = wid & 3;        // row 32-group
    int wc   = wid >> 2;       // col 64-half
    int q    = lane & 3;
    int tr   = lane >> 2;

    // stage W^T hi/lo once (padded layout identical in gmem -> bulk int4 copy)
    {
        const int4* srcH = (const int4*)(g_Whp + layer * DP);
        const int4* srcL = (const int4*)(g_Wlp + layer * DP);
        int4* dstH = (int4*)sm;
        int4* dstL = (int4*)(sm + DP);
        const int CH = DP * 2 / 16;   // 2176 int4 per array
        for (int i = tid; i < CH; i += 256) { dstH[i] = srcH[i]; dstL[i] = srcL[i]; }
    }
    if (tid < D) s_bias[tid] = bias[tid];

    uint32_t sWH = smem_u32(sm);
    uint32_t sWL = sWH + DP * 2;
    uint32_t sAH = sWH + 2 * DP * 2;
    uint32_t sAL = sWH + 3 * DP * 2;

    int lm_m = lane >> 3;
    int lm_r = lane & 7;
    // B (n-major rows): row-block from m>>1, k-halfblock from m&1
    uint32_t b_lm = (uint32_t)(8 * (lm_m >> 1) + lm_r) * (PW * 2) + (uint32_t)(lm_m & 1) * 16;
    // A (row-major): row from m&1, k-halfblock from m>>1
    uint32_t a_lm = (uint32_t)(8 * (lm_m & 1) + lm_r) * (PW * 2) + (uint32_t)(lm_m >> 1) * 16;

    for (int t = blockIdx.x; t < NTILES; t += gridDim.x) {
        int r0 = t * 128;

        // stage A tile hi/lo: 128 rows x 16 int4 (256B payload) -> padded rows
        {
            const int4* srcH = (const int4*)(g_Ah + (size_t)r0 * D);
            const int4* srcL = (const int4*)(g_Al + (size_t)r0 * D);
            int4* dstH = (int4*)(sm + 2 * DP);
            int4* dstL = (int4*)(sm + 3 * DP);
            const int4 z = make_int4(0, 0, 0, 0);
#pragma unroll
            for (int i = 0; i < 8; i++) {
                int idx = tid + i * 256;        // 0..2047
                int r = idx >> 4;
                int c = idx & 15;
                bool v = (r0 + r) < NN;
                int gidx = r * 16 + c;          // int4 index in row-major source
                dstH[r * 17 + c] = v ? srcH[gidx] : z;
                dstL[r * 17 + c] = v ? srcL[gidx] : z;
            }
        }
        __syncthreads();

        float acc[2][8][4];
#pragma unroll
        for (int m = 0; m < 2; m++)
#pragma unroll
            for (int j = 0; j < 8; j++)
#pragma unroll
                for (int c = 0; c < 4; c++) acc[m][j][c] = 0.f;

#pragma unroll
        for (int s = 0; s < 8; s++) {
            uint32_t aH[2][4], aL[2][4];
#pragma unroll
            for (int m = 0; m < 2; m++) {
                uint32_t ab = (uint32_t)(wm * 32 + m * 16) * (PW * 2) + (uint32_t)s * 32 + a_lm;
                LDSM_X4(aH[m], sAH + ab);
                LDSM_X4(aL[m], sAL + ab);
            }
#pragma unroll
            for (int p = 0; p < 4; p++) {     // ntile pairs (j = 2p, 2p+1)
                uint32_t nb = (uint32_t)(wc * 64 + p * 16) * (PW * 2) + (uint32_t)s * 32;
                uint32_t bH[4], bL[4];
                LDSM_X4(bH, sWH + nb + b_lm);
                LDSM_X4(bL, sWL + nb + b_lm);
#pragma unroll
                for (int m = 0; m < 2; m++) {
#pragma unroll
                    for (int u = 0; u < 2; u++) {
                        int j = 2 * p + u;
                        MMA16816(acc[m][j], aH[m], bH[2 * u], bH[2 * u + 1]);   // Ah*Bh
                        MMA16816(acc[m][j], aH[m], bL[2 * u], bL[2 * u + 1]);   // Ah*Bl
                        MMA16816(acc[m][j], aL[m], bH[2 * u], bH[2 * u + 1]);   // Al*Bh
                    }
                }
            }
        }

        // epilogue: bias + (relu * norm_src) fused; c0,c1 -> row, c2,c3 -> row+8
#pragma unroll
        for (int m = 0; m < 2; m++) {
            int ra = r0 + wm * 32 + m * 16 + tr;
            int rb = ra + 8;
            float nsa = 1.f, nsb = 1.f;
            if (relu_scale) {
                if (ra < NN) nsa = g_norm_src[ra];
                if (rb < NN) nsb = g_norm_src[rb];
            }
#pragma unroll
            for (int j = 0; j < 8; j++) {
                int col = wc * 64 + j * 8 + q * 2;
                float b0 = s_bias[col], b1 = s_bias[col + 1];
                float v0 = acc[m][j][0] + b0, v1 = acc[m][j][1] + b1;
                float v2 = acc[m][j][2] + b0, v3 = acc[m][j][3] + b1;
                if (relu_scale) {
                    // relu(x)*s == relu(x*s), s>0; store fp16 gather source
                    v0 = fmaxf(v0, 0.f) * nsa; v1 = fmaxf(v1, 0.f) * nsa;
                    v2 = fmaxf(v2, 0.f) * nsb; v3 = fmaxf(v3, 0.f) * nsb;
                    if (ra < NN) {
                        __half2 h = __floats2half2_rn(v0, v1);
                        *(uint32_t*)(&g_hs[(size_t)ra * D + col]) = h2_bits(h);
                    }
                    if (rb < NN) {
                        __half2 h = __floats2half2_rn(v2, v3);
                        *(uint32_t*)(&g_hs[(size_t)rb * D + col]) = h2_bits(h);
                    }
                } else {
                    if (ra < NN) *(float2*)(fout + (size_t)ra * D + col) = make_float2(v0, v1);
                    if (rb < NN) *(float2*)(fout + (size_t)rb * D + col) = make_float2(v2, v3);
                }
            }
        }
        __syncthreads();   // A buffer reuse barrier
    }
}

// ---------------- launch ----------------
extern "C" void kernel_launch(void* const* d_in, const int* in_sizes, int n_in,
                              void* d_out, int out_size) {
    const float* inputs = (const float*)d_in[0];   // [N,128]
    const float* Ws     = (const float*)d_in[1];   // [3,128,128]
    const float* bs     = (const float*)d_in[2];   // [3,128]
    const int*   src    = (const int*)d_in[3];     // [E]
    const int*   dst    = (const int*)d_in[4];     // [E]
    float*       out    = (float*)d_out;           // [N,128]

    const int gemm_smem = 4 * DP * (int)sizeof(__half);   // 139264
    cudaFuncSetAttribute(k_gemm_mma, cudaFuncAttributeMaxDynamicSharedMemorySize, gemm_smem);

    // graph preprocessing (every call; int atomics only)
    k_init_deg<<<(NN + 255) / 256, 256>>>();
    k_count<<<(NE + 255) / 256, 256>>>(src, dst);
    k_norm_alloc<<<(NN + 255) / 256, 256>>>();
    k_fill<<<(NE + 255) / 256, 256>>>(src, dst);

    // W split + layer-0 input scale (fp16 gather source)
    k_wprep<<<(3 * D * D + 255) / 256, 256>>>(Ws);
    k_scale0<<<(NN * (D / 4) + 255) / 256, 256>>>(inputs);

    const int agg_blocks = (NN * 32 + 255) / 256;   // warp per node

    for (int l = 0; l < 3; l++) {
        k_agg<<<agg_blocks, 256>>>();
        k_gemm_mma<<<148, 256, gemm_smem>>>(
            l, bs + l * D,
            (l < 2) ? 1 : 0,
            (l == 2) ? out : nullptr);
    }
}